// round 7
// baseline (speedup 1.0000x reference)
#include <cuda_runtime.h>
#include <cstddef>

#define IMH 1024
#define IMW 1024
#define SFRAMES 8
#define NB 4
#define TR 64            // tile rows (output)
#define TC 128           // tile cols
#define NTHREADS 512
#define GH (TR + 8)      // 72 rows incl vertical halo
#define GWF 136          // gray tile width incl horizontal halo (floats)
#define NT4 (GH * 34)    // 2448 float4 gray-load tasks
#define NVT ((TR / 2) * 34)   // 1088 vertical 2-row tasks
#define NHT (TR * 32)    // 2048 horizontal/output tasks

// smem layout (floats): sG[GH*GWF] | sVA[TR*GWF] | sVB[TR*GWF]
#define SMEM_FLOATS (GH * GWF + 2 * TR * GWF)
#define SMEM_BYTES  (SMEM_FLOATS * 4)      // 108,800 B -> 2 CTAs/SM

// 128 MB scratch for per-frame laplacian maps
__device__ float g_lap[(size_t)NB * SFRAMES * IMH * IMW];

__device__ __forceinline__ int reflect101(int i, int n) {
    if (i < 0) i = -i;
    if (i >= n) i = 2 * n - 2 - i;
    return i;
}

// ============================================================================
// Kernel A: per-frame laplacian-of-gaussian (composed 9x9, separable,
//           vertical-first) -> g_lap
// ============================================================================
extern "C" __global__ void __launch_bounds__(NTHREADS, 2)
lap_kernel(const float* __restrict__ x)
{
    extern __shared__ float smem[];
    float* sG  = smem;                      // GH x GWF gray (+halo)
    float* sVA = smem + GH * GWF;           // TR x GWF vertical A-filtered
    float* sVB = sVA + TR * GWF;            // TR x GWF vertical B-filtered

    const int tid = threadIdx.x;
    const int z   = blockIdx.z;             // b * SFRAMES + s
    const int hr0 = blockIdx.y * TR;
    const int wc0 = blockIdx.x * TC;
    const size_t HW = (size_t)IMH * IMW;
    const float ONE3 = 0.33333334f;

    const float* __restrict__ xf = x + (size_t)z * 3 * HW;

    // ==== Phase 1: gray tile load (flat, high-MLP) ====
    if (blockIdx.x != 0 && (int)blockIdx.x != (int)gridDim.x - 1) {
#pragma unroll
        for (int k = 0; k < 5; k++) {
            const int t = tid + k * NTHREADS;
            if (t < NT4) {
                const int r  = t / 34;
                const int c4 = t - r * 34;
                const int gr = reflect101(hr0 - 4 + r, IMH);
                const float* __restrict__ p = xf + (size_t)gr * IMW + (wc0 - 4 + c4 * 4);
                float4 a  = *reinterpret_cast<const float4*>(p);
                float4 bq = *reinterpret_cast<const float4*>(p + HW);
                float4 c  = *reinterpret_cast<const float4*>(p + 2 * HW);
                float4 g;
                g.x = (a.x + bq.x + c.x) * ONE3;
                g.y = (a.y + bq.y + c.y) * ONE3;
                g.z = (a.z + bq.z + c.z) * ONE3;
                g.w = (a.w + bq.w + c.w) * ONE3;
                *reinterpret_cast<float4*>(&sG[r * GWF + c4 * 4]) = g;
            }
        }
    } else {
        // edge blocks: scalar path with full reflect
        for (int i = tid; i < GH * GWF; i += NTHREADS) {
            const int r = i / GWF;
            const int c = i - r * GWF;
            const int gr = reflect101(hr0 - 4 + r, IMH);
            const int gc = reflect101(wc0 - 4 + c, IMW);
            const float* __restrict__ p = xf + (size_t)gr * IMW + gc;
            sG[i] = (__ldg(p) + __ldg(p + HW) + __ldg(p + 2 * HW)) * ONE3;
        }
    }
    __syncthreads();

    // ==== Phase 2: vertical 9-tap A&B, 2-row sliding window ====
    // wA = [.0625,.5,1.75,3.5,4.375,3.5,1.75,.5,.0625]
    // wB = [.0625,.25,.25,-.25,-.625,-.25,.25,.25,.0625]
    {
        const float wAv[9] = {0.0625f, 0.5f, 1.75f, 3.5f, 4.375f, 3.5f, 1.75f, 0.5f, 0.0625f};
        const float wBv[9] = {0.0625f, 0.25f, 0.25f, -0.25f, -0.625f, -0.25f, 0.25f, 0.25f, 0.0625f};
#pragma unroll
        for (int k = 0; k < 3; k++) {
            const int t = tid + k * NTHREADS;
            if (t < NVT) {
                const int rb = t / 34;          // 2-row block
                const int c4 = t - rb * 34;
                const int r0 = rb * 2;
                float4 g[10];
#pragma unroll
                for (int j = 0; j < 10; j++)
                    g[j] = *reinterpret_cast<const float4*>(&sG[(r0 + j) * GWF + c4 * 4]);

                float4 a0, b0, a1, b1;
#pragma unroll
                for (int o = 0; o < 4; o++) {
                    float accA0 = 0.f, accB0 = 0.f, accA1 = 0.f, accB1 = 0.f;
#pragma unroll
                    for (int j = 0; j < 9; j++) {
                        const float v0 = (&g[j].x)[o];
                        const float v1 = (&g[j + 1].x)[o];
                        accA0 += wAv[j] * v0;
                        accB0 += wBv[j] * v0;
                        accA1 += wAv[j] * v1;
                        accB1 += wBv[j] * v1;
                    }
                    (&a0.x)[o] = accA0; (&b0.x)[o] = accB0;
                    (&a1.x)[o] = accA1; (&b1.x)[o] = accB1;
                }
                *reinterpret_cast<float4*>(&sVA[r0 * GWF + c4 * 4])       = a0;
                *reinterpret_cast<float4*>(&sVA[(r0 + 1) * GWF + c4 * 4]) = a1;
                *reinterpret_cast<float4*>(&sVB[r0 * GWF + c4 * 4])       = b0;
                *reinterpret_cast<float4*>(&sVB[(r0 + 1) * GWF + c4 * 4]) = b1;
            }
        }
    }
    __syncthreads();

    // ==== Phase 3: horizontal 9-tap (B on vA + A on vB) -> g_lap ====
#pragma unroll
    for (int k = 0; k < 4; k++) {
        const int t  = tid + k * NTHREADS;      // NHT = 2048 exactly
        const int r  = t >> 5;
        const int cg = t & 31;
        const int base = r * GWF + cg * 4;
        float va[12], vb[12];
#pragma unroll
        for (int j = 0; j < 12; j += 4) {
            *reinterpret_cast<float4*>(&va[j]) = *reinterpret_cast<const float4*>(&sVA[base + j]);
            *reinterpret_cast<float4*>(&vb[j]) = *reinterpret_cast<const float4*>(&sVB[base + j]);
        }
        float4 lap4;
#pragma unroll
        for (int o = 0; o < 4; o++) {
            float p1a = va[o + 3] + va[o + 5];
            float p2a = va[o + 2] + va[o + 6];
            float p3a = va[o + 1] + va[o + 7];
            float p4a = va[o + 0] + va[o + 8];
            float p1b = vb[o + 3] + vb[o + 5];
            float p2b = vb[o + 2] + vb[o + 6];
            float p3b = vb[o + 1] + vb[o + 7];
            float p4b = vb[o + 0] + vb[o + 8];
            (&lap4.x)[o] =
                  -0.625f * va[o + 4] - 0.25f * p1a + 0.25f * p2a + 0.25f * p3a + 0.0625f * p4a
                +  4.375f * vb[o + 4] + 3.5f  * p1b + 1.75f * p2b + 0.5f  * p3b + 0.0625f * p4b;
        }
        const size_t off = (size_t)z * HW + (size_t)(hr0 + r) * IMW + wc0 + cg * 4;
        *reinterpret_cast<float4*>(&g_lap[off]) = lap4;
    }
}

// ============================================================================
// Kernel B: per-pixel argmax over 8 frames + RGB gather (83us @ 85% DRAM -- keep)
// ============================================================================
#define BTHREADS 256
#define PXPT 4    // pixels per thread (one float4)

extern "C" __global__ void __launch_bounds__(BTHREADS)
merge_kernel(const float* __restrict__ x, float* __restrict__ out)
{
    const int b = blockIdx.y;
    const size_t HW = (size_t)IMH * IMW;
    const size_t p = ((size_t)blockIdx.x * BTHREADS + threadIdx.x) * PXPT;

    const float* __restrict__ lapb = g_lap + (size_t)b * SFRAMES * HW;

    float best0 = -3.0e38f, best1 = -3.0e38f, best2 = -3.0e38f, best3 = -3.0e38f;
    unsigned i0 = 0, i1 = 0, i2 = 0, i3 = 0;
#pragma unroll
    for (int s = 0; s < SFRAMES; s++) {
        float4 v = __ldg(reinterpret_cast<const float4*>(lapb + s * HW + p));
        if (v.x > best0) { best0 = v.x; i0 = s; }
        if (v.y > best1) { best1 = v.y; i1 = s; }
        if (v.z > best2) { best2 = v.z; i2 = s; }
        if (v.w > best3) { best3 = v.w; i3 = s; }
    }

    const float* __restrict__ xb = x + (size_t)b * SFRAMES * 3 * HW;
    unsigned idx[4] = {i0, i1, i2, i3};
    float R[4], G[4], B[4];
#pragma unroll
    for (int o = 0; o < 4; o++) {
        const float* __restrict__ xw = xb + (size_t)idx[o] * 3 * HW + p + o;
        R[o] = __ldg(xw);
        G[o] = __ldg(xw + HW);
        B[o] = __ldg(xw + 2 * HW);
    }

    float* __restrict__ ob = out + (size_t)b * 3 * HW + p;
    *reinterpret_cast<float4*>(ob)          = make_float4(R[0], R[1], R[2], R[3]);
    *reinterpret_cast<float4*>(ob + HW)     = make_float4(G[0], G[1], G[2], G[3]);
    *reinterpret_cast<float4*>(ob + 2 * HW) = make_float4(B[0], B[1], B[2], B[3]);
}

// ============================================================================
extern "C" void kernel_launch(void* const* d_in, const int* in_sizes, int n_in,
                              void* d_out, int out_size)
{
    const float* x = (const float*)d_in[0];
    float* out = (float*)d_out;

    cudaFuncSetAttribute(lap_kernel,
                         cudaFuncAttributeMaxDynamicSharedMemorySize, SMEM_BYTES);

    dim3 gridA(IMW / TC, IMH / TR, NB * SFRAMES);
    lap_kernel<<<gridA, NTHREADS, SMEM_BYTES>>>(x);

    dim3 gridB((IMH * IMW) / (BTHREADS * PXPT), NB);
    merge_kernel<<<gridB, BTHREADS>>>(x, out);
}

// round 8
// speedup vs baseline: 1.2573x; 1.2573x over previous
#include <cuda_runtime.h>
#include <cstddef>

#define IMH 1024
#define IMW 1024
#define SFRAMES 8
#define NB 4
#define TR 32            // tile rows (output)
#define TC 64            // tile cols
#define NTHREADS 256
#define GH (TR + 8)      // 40 rows incl vertical halo
#define GWF (TC + 8)     // 72: gray tile width incl horizontal halo (floats)
#define NT4 (GH * (GWF / 4))   // 720 float4 gray-load tasks (18 per row)
#define NHT (GH * (TC / 4))    // 640 hconv tasks
#define NVT (TR * (TC / 4))    // 512 vconv tasks

// smem layout (floats): sG[GH*GWF] | sHA[GH*TC] | sHB[GH*TC]
#define SMEM_FLOATS (GH * GWF + 2 * GH * TC)
#define SMEM_BYTES  (SMEM_FLOATS * 4)      // 32,000 B -> 6 CTAs/SM

// 4 MB scratch: per-pixel winning frame index
__device__ unsigned char g_idx[(size_t)NB * IMH * IMW];

__device__ __forceinline__ int reflect101(int i, int n) {
    if (i < 0) i = -i;
    if (i >= n) i = 2 * n - 2 - i;
    return i;
}

// ============================================================================
// Kernel A: fused 8-frame laplacian-of-gaussian + argmax -> u8 index map
// ============================================================================
extern "C" __global__ void __launch_bounds__(NTHREADS, 6)
lap_argmax_kernel(const float* __restrict__ x)
{
    extern __shared__ float smem[];
    float* sG  = smem;                      // GH x GWF gray (+halo)
    float* sHA = smem + GH * GWF;           // GH x TC horizontal A-filtered
    float* sHB = sHA + GH * TC;             // GH x TC horizontal B-filtered

    const int tid = threadIdx.x;
    const int b   = blockIdx.z;
    const int hr0 = blockIdx.y * TR;
    const int wc0 = blockIdx.x * TC;
    const size_t HW = (size_t)IMH * IMW;
    const float ONE3 = 0.33333334f;
    const bool interior = (blockIdx.x != 0) && ((int)blockIdx.x != (int)gridDim.x - 1);

    // per-thread argmax state: 8 px = 2 groups of 4 consecutive cols
    float bestLap[2][4];
    unsigned packedIdx = 0;                 // 8 x 4-bit frame indices
#pragma unroll
    for (int it = 0; it < 2; it++)
#pragma unroll
        for (int o = 0; o < 4; o++) bestLap[it][o] = -3.0e38f;

    for (int s = 0; s < SFRAMES; s++) {
        const float* __restrict__ xf = x + ((size_t)(b * SFRAMES + s)) * 3 * HW;

        // ==== Phase 1: gray tile load (flat, high-MLP) ====
        if (interior) {
#pragma unroll
            for (int k = 0; k < 3; k++) {
                const int t = tid + k * NTHREADS;
                if (t < NT4) {
                    const int r  = t / (GWF / 4);
                    const int c4 = t - r * (GWF / 4);
                    const int gr = reflect101(hr0 - 4 + r, IMH);
                    const float* __restrict__ p = xf + (size_t)gr * IMW + (wc0 - 4 + c4 * 4);
                    float4 a  = *reinterpret_cast<const float4*>(p);
                    float4 bq = *reinterpret_cast<const float4*>(p + HW);
                    float4 c  = *reinterpret_cast<const float4*>(p + 2 * HW);
                    float4 g;
                    g.x = (a.x + bq.x + c.x) * ONE3;
                    g.y = (a.y + bq.y + c.y) * ONE3;
                    g.z = (a.z + bq.z + c.z) * ONE3;
                    g.w = (a.w + bq.w + c.w) * ONE3;
                    *reinterpret_cast<float4*>(&sG[r * GWF + c4 * 4]) = g;
                }
            }
        } else {
            for (int i = tid; i < GH * GWF; i += NTHREADS) {
                const int r = i / GWF;
                const int c = i - r * GWF;
                const int gr = reflect101(hr0 - 4 + r, IMH);
                const int gc = reflect101(wc0 - 4 + c, IMW);
                const float* __restrict__ p = xf + (size_t)gr * IMW + gc;
                sG[i] = (__ldg(p) + __ldg(p + HW) + __ldg(p + 2 * HW)) * ONE3;
            }
        }
        __syncthreads();

        // ==== Phase 2: horizontal 9-tap A/B from sG -> sHA/sHB ====
#pragma unroll
        for (int k = 0; k < 3; k++) {
            const int t = tid + k * NTHREADS;
            if (t < NHT) {
                const int r  = t / (TC / 4);
                const int cg = t - r * (TC / 4);
                float w[12];
#pragma unroll
                for (int j = 0; j < 12; j += 4)
                    *reinterpret_cast<float4*>(&w[j]) =
                        *reinterpret_cast<const float4*>(&sG[r * GWF + cg * 4 + j]);
                float4 hA4, hB4;
#pragma unroll
                for (int o = 0; o < 4; o++) {
                    float p1 = w[o + 3] + w[o + 5];
                    float p2 = w[o + 2] + w[o + 6];
                    float p3 = w[o + 1] + w[o + 7];
                    float p4 = w[o + 0] + w[o + 8];
                    float ctr = w[o + 4];
                    (&hA4.x)[o] =  4.375f * ctr + 3.5f  * p1 + 1.75f * p2 + 0.5f  * p3 + 0.0625f * p4;
                    (&hB4.x)[o] = -0.625f * ctr - 0.25f * p1 + 0.25f * p2 + 0.25f * p3 + 0.0625f * p4;
                }
                *reinterpret_cast<float4*>(&sHA[r * TC + cg * 4]) = hA4;
                *reinterpret_cast<float4*>(&sHB[r * TC + cg * 4]) = hB4;
            }
        }
        __syncthreads();

        // ==== Phase 3: vertical 9-tap (B on hA + A on hB) + argmax ====
        {
            const float wAv[9] = {0.0625f, 0.5f, 1.75f, 3.5f, 4.375f, 3.5f, 1.75f, 0.5f, 0.0625f};
            const float wBv[9] = {0.0625f, 0.25f, 0.25f, -0.25f, -0.625f, -0.25f, 0.25f, 0.25f, 0.0625f};
#pragma unroll
            for (int it = 0; it < 2; it++) {
                const int t  = tid + it * NTHREADS;   // NVT = 512 exactly
                const int r  = t >> 4;
                const int cg = t & 15;
                const int base = r * TC + cg * 4;
                float acc0 = 0.f, acc1 = 0.f, acc2 = 0.f, acc3 = 0.f;
#pragma unroll
                for (int j = 0; j < 9; j++) {
                    float4 ha = *reinterpret_cast<const float4*>(&sHA[base + j * TC]);
                    float4 hb = *reinterpret_cast<const float4*>(&sHB[base + j * TC]);
                    acc0 += wBv[j] * ha.x + wAv[j] * hb.x;
                    acc1 += wBv[j] * ha.y + wAv[j] * hb.y;
                    acc2 += wBv[j] * ha.z + wAv[j] * hb.z;
                    acc3 += wBv[j] * ha.w + wAv[j] * hb.w;
                }
                float lap[4] = {acc0, acc1, acc2, acc3};
#pragma unroll
                for (int o = 0; o < 4; o++) {
                    const int sh = (it * 4 + o) * 4;
                    if (lap[o] > bestLap[it][o]) {    // strict > == first-max (jnp.argmax)
                        bestLap[it][o] = lap[o];
                        packedIdx = (packedIdx & ~(0xFu << sh)) | ((unsigned)s << sh);
                    }
                }
            }
        }
        __syncthreads();   // sG/sHA/sHB reused by next frame
    }

    // ==== Epilogue: write u8 index map ====
#pragma unroll
    for (int it = 0; it < 2; it++) {
        const int t  = tid + it * NTHREADS;
        const int r  = t >> 4;
        const int cg = t & 15;
        uchar4 q;
        q.x = (packedIdx >> ((it * 4 + 0) * 4)) & 0xF;
        q.y = (packedIdx >> ((it * 4 + 1) * 4)) & 0xF;
        q.z = (packedIdx >> ((it * 4 + 2) * 4)) & 0xF;
        q.w = (packedIdx >> ((it * 4 + 3) * 4)) & 0xF;
        const size_t off = (size_t)b * HW + (size_t)(hr0 + r) * IMW + wc0 + cg * 4;
        *reinterpret_cast<uchar4*>(&g_idx[off]) = q;
    }
}

// ============================================================================
// Kernel B: gather winner RGB per pixel -> out
// ============================================================================
#define BTHREADS 256
#define PXPT 4    // pixels per thread

extern "C" __global__ void __launch_bounds__(BTHREADS)
gather_kernel(const float* __restrict__ x, float* __restrict__ out)
{
    const int b = blockIdx.y;
    const size_t HW = (size_t)IMH * IMW;
    const size_t p = ((size_t)blockIdx.x * BTHREADS + threadIdx.x) * PXPT;

    uchar4 q = *reinterpret_cast<const uchar4*>(&g_idx[(size_t)b * HW + p]);
    unsigned idx[4] = {q.x, q.y, q.z, q.w};

    const float* __restrict__ xb = x + (size_t)b * SFRAMES * 3 * HW;
    float R[4], G[4], B[4];
#pragma unroll
    for (int o = 0; o < 4; o++) {
        const float* __restrict__ xw = xb + (size_t)idx[o] * 3 * HW + p + o;
        R[o] = __ldg(xw);
        G[o] = __ldg(xw + HW);
        B[o] = __ldg(xw + 2 * HW);
    }

    float* __restrict__ ob = out + (size_t)b * 3 * HW + p;
    *reinterpret_cast<float4*>(ob)          = make_float4(R[0], R[1], R[2], R[3]);
    *reinterpret_cast<float4*>(ob + HW)     = make_float4(G[0], G[1], G[2], G[3]);
    *reinterpret_cast<float4*>(ob + 2 * HW) = make_float4(B[0], B[1], B[2], B[3]);
}

// ============================================================================
extern "C" void kernel_launch(void* const* d_in, const int* in_sizes, int n_in,
                              void* d_out, int out_size)
{
    const float* x = (const float*)d_in[0];
    float* out = (float*)d_out;

    cudaFuncSetAttribute(lap_argmax_kernel,
                         cudaFuncAttributeMaxDynamicSharedMemorySize, SMEM_BYTES);

    dim3 gridA(IMW / TC, IMH / TR, NB);
    lap_argmax_kernel<<<gridA, NTHREADS, SMEM_BYTES>>>(x);

    dim3 gridB((IMH * IMW) / (BTHREADS * PXPT), NB);
    gather_kernel<<<gridB, BTHREADS>>>(x, out);
}

// round 9
// speedup vs baseline: 1.5425x; 1.2268x over previous
#include <cuda_runtime.h>
#include <cstddef>

#define IMH 1024
#define IMW 1024
#define SFRAMES 8
#define NB 4
#define TR 32            // tile rows (output)
#define TC 64            // tile cols
#define NTHREADS 256
#define GH (TR + 8)      // 40 rows incl vertical halo
#define GWF (TC + 8)     // 72: gray tile width incl horizontal halo (floats)
#define NT4 (GH * (GWF / 4))   // 720 float4 gray-load tasks (18 per row)
#define NHT (GH * (TC / 4))    // 640 hconv tasks
#define NVT (TR * (TC / 4))    // 512 vconv tasks

// smem layout (floats): sG[GH*GWF] | sHA[GH*TC] | sHB[GH*TC]
#define SMEM_FLOATS (GH * GWF + 2 * GH * TC)
#define SMEM_BYTES  (SMEM_FLOATS * 4)      // 32,000 B

__device__ __forceinline__ int reflect101(int i, int n) {
    if (i < 0) i = -i;
    if (i >= n) i = 2 * n - 2 - i;
    return i;
}

// ============================================================================
// Fused: 8-frame laplacian-of-gaussian + argmax + L1-hot winner RGB tracking
// ============================================================================
extern "C" __global__ void __launch_bounds__(NTHREADS, 4)
lap_merge_kernel(const float* __restrict__ x, float* __restrict__ out)
{
    extern __shared__ float smem[];
    float* sG  = smem;                      // GH x GWF gray (+halo)
    float* sHA = smem + GH * GWF;           // GH x TC horizontal A-filtered
    float* sHB = sHA + GH * TC;             // GH x TC horizontal B-filtered

    const int tid = threadIdx.x;
    const int b   = blockIdx.z;
    const int hr0 = blockIdx.y * TR;
    const int wc0 = blockIdx.x * TC;
    const size_t HW = (size_t)IMH * IMW;
    const float ONE3 = 0.33333334f;
    const bool interior = (blockIdx.x != 0) && ((int)blockIdx.x != (int)gridDim.x - 1);

    // per-thread state: 8 px = 2 groups of 4 consecutive cols
    float bestLap[2][4], bR[2][4], bG[2][4], bB[2][4];
#pragma unroll
    for (int it = 0; it < 2; it++)
#pragma unroll
        for (int o = 0; o < 4; o++) bestLap[it][o] = -3.0e38f;

    for (int s = 0; s < SFRAMES; s++) {
        const float* __restrict__ xf = x + ((size_t)(b * SFRAMES + s)) * 3 * HW;

        // ==== Phase 1: gray tile load (flat, high-MLP) ====
        if (interior) {
#pragma unroll
            for (int k = 0; k < 3; k++) {
                const int t = tid + k * NTHREADS;
                if (t < NT4) {
                    const int r  = t / (GWF / 4);
                    const int c4 = t - r * (GWF / 4);
                    const int gr = reflect101(hr0 - 4 + r, IMH);
                    const float* __restrict__ p = xf + (size_t)gr * IMW + (wc0 - 4 + c4 * 4);
                    float4 a  = *reinterpret_cast<const float4*>(p);
                    float4 bq = *reinterpret_cast<const float4*>(p + HW);
                    float4 c  = *reinterpret_cast<const float4*>(p + 2 * HW);
                    float4 g;
                    g.x = (a.x + bq.x + c.x) * ONE3;
                    g.y = (a.y + bq.y + c.y) * ONE3;
                    g.z = (a.z + bq.z + c.z) * ONE3;
                    g.w = (a.w + bq.w + c.w) * ONE3;
                    *reinterpret_cast<float4*>(&sG[r * GWF + c4 * 4]) = g;
                }
            }
        } else {
            for (int i = tid; i < GH * GWF; i += NTHREADS) {
                const int r = i / GWF;
                const int c = i - r * GWF;
                const int gr = reflect101(hr0 - 4 + r, IMH);
                const int gc = reflect101(wc0 - 4 + c, IMW);
                const float* __restrict__ p = xf + (size_t)gr * IMW + gc;
                sG[i] = (__ldg(p) + __ldg(p + HW) + __ldg(p + 2 * HW)) * ONE3;
            }
        }
        __syncthreads();

        // ==== Phase 2: horizontal 9-tap A/B from sG -> sHA/sHB ====
#pragma unroll
        for (int k = 0; k < 3; k++) {
            const int t = tid + k * NTHREADS;
            if (t < NHT) {
                const int r  = t / (TC / 4);
                const int cg = t - r * (TC / 4);
                float w[12];
#pragma unroll
                for (int j = 0; j < 12; j += 4)
                    *reinterpret_cast<float4*>(&w[j]) =
                        *reinterpret_cast<const float4*>(&sG[r * GWF + cg * 4 + j]);
                float4 hA4, hB4;
#pragma unroll
                for (int o = 0; o < 4; o++) {
                    float p1 = w[o + 3] + w[o + 5];
                    float p2 = w[o + 2] + w[o + 6];
                    float p3 = w[o + 1] + w[o + 7];
                    float p4 = w[o + 0] + w[o + 8];
                    float ctr = w[o + 4];
                    (&hA4.x)[o] =  4.375f * ctr + 3.5f  * p1 + 1.75f * p2 + 0.5f  * p3 + 0.0625f * p4;
                    (&hB4.x)[o] = -0.625f * ctr - 0.25f * p1 + 0.25f * p2 + 0.25f * p3 + 0.0625f * p4;
                }
                *reinterpret_cast<float4*>(&sHA[r * TC + cg * 4]) = hA4;
                *reinterpret_cast<float4*>(&sHB[r * TC + cg * 4]) = hB4;
            }
        }
        __syncthreads();

        // ==== Phase 3: vertical 9-tap (B on hA + A on hB) + argmax + L1-hot reload ====
        {
            const float wAv[9] = {0.0625f, 0.5f, 1.75f, 3.5f, 4.375f, 3.5f, 1.75f, 0.5f, 0.0625f};
            const float wBv[9] = {0.0625f, 0.25f, 0.25f, -0.25f, -0.625f, -0.25f, 0.25f, 0.25f, 0.0625f};
#pragma unroll
            for (int it = 0; it < 2; it++) {
                const int t  = tid + it * NTHREADS;   // NVT = 512 exactly
                const int r  = t >> 4;
                const int cg = t & 15;
                const int base = r * TC + cg * 4;
                float acc0 = 0.f, acc1 = 0.f, acc2 = 0.f, acc3 = 0.f;
#pragma unroll
                for (int j = 0; j < 9; j++) {
                    float4 ha = *reinterpret_cast<const float4*>(&sHA[base + j * TC]);
                    float4 hb = *reinterpret_cast<const float4*>(&sHB[base + j * TC]);
                    acc0 += wBv[j] * ha.x + wAv[j] * hb.x;
                    acc1 += wBv[j] * ha.y + wAv[j] * hb.y;
                    acc2 += wBv[j] * ha.z + wAv[j] * hb.z;
                    acc3 += wBv[j] * ha.w + wAv[j] * hb.w;
                }
                float lap[4] = {acc0, acc1, acc2, acc3};
                const size_t pix = (size_t)(hr0 + r) * IMW + (wc0 + cg * 4);
#pragma unroll
                for (int o = 0; o < 4; o++) {
                    if (lap[o] > bestLap[it][o]) {    // strict > == first-max (jnp.argmax)
                        bestLap[it][o] = lap[o];
                        // reload winner RGB: these bytes were read by phase 1 -> L1 hit
                        const float* __restrict__ xw = xf + pix + o;
                        bR[it][o] = __ldg(xw);
                        bG[it][o] = __ldg(xw + HW);
                        bB[it][o] = __ldg(xw + 2 * HW);
                    }
                }
            }
        }
        __syncthreads();   // sG/sHA/sHB reused by next frame
    }

    // ==== Epilogue: write winner RGB (b, c, h, w) ====
#pragma unroll
    for (int it = 0; it < 2; it++) {
        const int t  = tid + it * NTHREADS;
        const int r  = t >> 4;
        const int cg = t & 15;
        const size_t obase = ((size_t)(b * 3) * IMH + (hr0 + r)) * IMW + wc0 + cg * 4;
        *reinterpret_cast<float4*>(out + obase) =
            make_float4(bR[it][0], bR[it][1], bR[it][2], bR[it][3]);
        *reinterpret_cast<float4*>(out + obase + HW) =
            make_float4(bG[it][0], bG[it][1], bG[it][2], bG[it][3]);
        *reinterpret_cast<float4*>(out + obase + 2 * HW) =
            make_float4(bB[it][0], bB[it][1], bB[it][2], bB[it][3]);
    }
}

// ============================================================================
extern "C" void kernel_launch(void* const* d_in, const int* in_sizes, int n_in,
                              void* d_out, int out_size)
{
    const float* x = (const float*)d_in[0];
    float* out = (float*)d_out;

    cudaFuncSetAttribute(lap_merge_kernel,
                         cudaFuncAttributeMaxDynamicSharedMemorySize, SMEM_BYTES);

    dim3 grid(IMW / TC, IMH / TR, NB);
    lap_merge_kernel<<<grid, NTHREADS, SMEM_BYTES>>>(x, out);
}

// round 10
// speedup vs baseline: 1.8026x; 1.1686x over previous
#include <cuda_runtime.h>
#include <cstddef>

#define IMH 1024
#define IMW 1024
#define SFRAMES 8
#define NB 4
#define TR 32            // tile rows (output)
#define TC 64            // tile cols
#define NTHREADS 256
#define GH (TR + 8)      // 40 rows incl vertical halo
#define GWF (TC + 8)     // 72: gray tile width incl horizontal halo (floats)
#define NT4 (GH * (GWF / 4))   // 720 float4 gray-load tasks (18 per row)
#define NHT (GH * (TC / 4))    // 640 hconv tasks

// smem layout (floats): sG[GH*GWF] | sHA[GH*TC] | sHB[GH*TC]
#define SMEM_FLOATS (GH * GWF + 2 * GH * TC)
#define SMEM_BYTES  (SMEM_FLOATS * 4)      // 32,000 B

__device__ __forceinline__ int reflect101(int i, int n) {
    if (i < 0) i = -i;
    if (i >= n) i = 2 * n - 2 - i;
    return i;
}

// ============================================================================
// Fused: 8-frame laplacian-of-gaussian + argmax + L1-hot winner RGB tracking
// Phase 3 uses 2-row blocking: 10-row shared window -> 2 output rows.
// ============================================================================
extern "C" __global__ void __launch_bounds__(NTHREADS, 4)
lap_merge_kernel(const float* __restrict__ x, float* __restrict__ out)
{
    extern __shared__ float smem[];
    float* sG  = smem;                      // GH x GWF gray (+halo)
    float* sHA = smem + GH * GWF;           // GH x TC horizontal A-filtered
    float* sHB = sHA + GH * TC;             // GH x TC horizontal B-filtered

    const int tid = threadIdx.x;
    const int b   = blockIdx.z;
    const int hr0 = blockIdx.y * TR;
    const int wc0 = blockIdx.x * TC;
    const size_t HW = (size_t)IMH * IMW;
    const float ONE3 = 0.33333334f;
    const bool interior = (blockIdx.x != 0) && ((int)blockIdx.x != (int)gridDim.x - 1);

    // per-thread state: 8 px = 2 rows x 4 consecutive cols
    const int r0 = (tid >> 4) * 2;          // 16 groups x 2 rows = 32 rows
    const int cg = tid & 15;                // 16 col-groups x 4 = 64 cols

    float bestLap[2][4], bR[2][4], bG[2][4], bB[2][4];
#pragma unroll
    for (int rr = 0; rr < 2; rr++)
#pragma unroll
        for (int o = 0; o < 4; o++) bestLap[rr][o] = -3.0e38f;

    for (int s = 0; s < SFRAMES; s++) {
        const float* __restrict__ xf = x + ((size_t)(b * SFRAMES + s)) * 3 * HW;

        // ==== Phase 1: gray tile load (flat, high-MLP) ====
        if (interior) {
#pragma unroll
            for (int k = 0; k < 3; k++) {
                const int t = tid + k * NTHREADS;
                if (t < NT4) {
                    const int r  = t / (GWF / 4);
                    const int c4 = t - r * (GWF / 4);
                    const int gr = reflect101(hr0 - 4 + r, IMH);
                    const float* __restrict__ p = xf + (size_t)gr * IMW + (wc0 - 4 + c4 * 4);
                    float4 a  = *reinterpret_cast<const float4*>(p);
                    float4 bq = *reinterpret_cast<const float4*>(p + HW);
                    float4 c  = *reinterpret_cast<const float4*>(p + 2 * HW);
                    float4 g;
                    g.x = (a.x + bq.x + c.x) * ONE3;
                    g.y = (a.y + bq.y + c.y) * ONE3;
                    g.z = (a.z + bq.z + c.z) * ONE3;
                    g.w = (a.w + bq.w + c.w) * ONE3;
                    *reinterpret_cast<float4*>(&sG[r * GWF + c4 * 4]) = g;
                }
            }
        } else {
            for (int i = tid; i < GH * GWF; i += NTHREADS) {
                const int r = i / GWF;
                const int c = i - r * GWF;
                const int gr = reflect101(hr0 - 4 + r, IMH);
                const int gc = reflect101(wc0 - 4 + c, IMW);
                const float* __restrict__ p = xf + (size_t)gr * IMW + gc;
                sG[i] = (__ldg(p) + __ldg(p + HW) + __ldg(p + 2 * HW)) * ONE3;
            }
        }
        __syncthreads();

        // ==== Phase 2: horizontal 9-tap A/B from sG -> sHA/sHB ====
#pragma unroll
        for (int k = 0; k < 3; k++) {
            const int t = tid + k * NTHREADS;
            if (t < NHT) {
                const int r  = t / (TC / 4);
                const int c2 = t - r * (TC / 4);
                float w[12];
#pragma unroll
                for (int j = 0; j < 12; j += 4)
                    *reinterpret_cast<float4*>(&w[j]) =
                        *reinterpret_cast<const float4*>(&sG[r * GWF + c2 * 4 + j]);
                float4 hA4, hB4;
#pragma unroll
                for (int o = 0; o < 4; o++) {
                    float p1 = w[o + 3] + w[o + 5];
                    float p2 = w[o + 2] + w[o + 6];
                    float p3 = w[o + 1] + w[o + 7];
                    float p4 = w[o + 0] + w[o + 8];
                    float ctr = w[o + 4];
                    (&hA4.x)[o] =  4.375f * ctr + 3.5f  * p1 + 1.75f * p2 + 0.5f  * p3 + 0.0625f * p4;
                    (&hB4.x)[o] = -0.625f * ctr - 0.25f * p1 + 0.25f * p2 + 0.25f * p3 + 0.0625f * p4;
                }
                *reinterpret_cast<float4*>(&sHA[r * TC + c2 * 4]) = hA4;
                *reinterpret_cast<float4*>(&sHB[r * TC + c2 * 4]) = hB4;
            }
        }
        __syncthreads();

        // ==== Phase 3: vertical 9-tap (B on hA + A on hB), 2-row window + argmax ====
        {
            const float wAv[9] = {0.0625f, 0.5f, 1.75f, 3.5f, 4.375f, 3.5f, 1.75f, 0.5f, 0.0625f};
            const float wBv[9] = {0.0625f, 0.25f, 0.25f, -0.25f, -0.625f, -0.25f, 0.25f, 0.25f, 0.0625f};
            float acc[2][4];
#pragma unroll
            for (int rr = 0; rr < 2; rr++)
#pragma unroll
                for (int o = 0; o < 4; o++) acc[rr][o] = 0.f;

#pragma unroll
            for (int j = 0; j < 10; j++) {
                float4 ha = *reinterpret_cast<const float4*>(&sHA[(r0 + j) * TC + cg * 4]);
                float4 hb = *reinterpret_cast<const float4*>(&sHB[(r0 + j) * TC + cg * 4]);
                if (j < 9) {
                    acc[0][0] += wBv[j] * ha.x + wAv[j] * hb.x;
                    acc[0][1] += wBv[j] * ha.y + wAv[j] * hb.y;
                    acc[0][2] += wBv[j] * ha.z + wAv[j] * hb.z;
                    acc[0][3] += wBv[j] * ha.w + wAv[j] * hb.w;
                }
                if (j > 0) {
                    acc[1][0] += wBv[j - 1] * ha.x + wAv[j - 1] * hb.x;
                    acc[1][1] += wBv[j - 1] * ha.y + wAv[j - 1] * hb.y;
                    acc[1][2] += wBv[j - 1] * ha.z + wAv[j - 1] * hb.z;
                    acc[1][3] += wBv[j - 1] * ha.w + wAv[j - 1] * hb.w;
                }
            }
#pragma unroll
            for (int rr = 0; rr < 2; rr++) {
                const size_t pix = (size_t)(hr0 + r0 + rr) * IMW + (wc0 + cg * 4);
#pragma unroll
                for (int o = 0; o < 4; o++) {
                    if (acc[rr][o] > bestLap[rr][o]) {  // strict > == first-max (jnp.argmax)
                        bestLap[rr][o] = acc[rr][o];
                        // winner RGB reload: bytes just read by phase 1 -> L1 hit
                        const float* __restrict__ xw = xf + pix + o;
                        bR[rr][o] = __ldg(xw);
                        bG[rr][o] = __ldg(xw + HW);
                        bB[rr][o] = __ldg(xw + 2 * HW);
                    }
                }
            }
        }
        __syncthreads();   // sG/sHA/sHB reused by next frame
    }

    // ==== Epilogue: write winner RGB (b, c, h, w) ====
#pragma unroll
    for (int rr = 0; rr < 2; rr++) {
        const size_t obase = ((size_t)(b * 3) * IMH + (hr0 + r0 + rr)) * IMW + wc0 + cg * 4;
        *reinterpret_cast<float4*>(out + obase) =
            make_float4(bR[rr][0], bR[rr][1], bR[rr][2], bR[rr][3]);
        *reinterpret_cast<float4*>(out + obase + HW) =
            make_float4(bG[rr][0], bG[rr][1], bG[rr][2], bG[rr][3]);
        *reinterpret_cast<float4*>(out + obase + 2 * HW) =
            make_float4(bB[rr][0], bB[rr][1], bB[rr][2], bB[rr][3]);
    }
}

// ============================================================================
extern "C" void kernel_launch(void* const* d_in, const int* in_sizes, int n_in,
                              void* d_out, int out_size)
{
    const float* x = (const float*)d_in[0];
    float* out = (float*)d_out;

    cudaFuncSetAttribute(lap_merge_kernel,
                         cudaFuncAttributeMaxDynamicSharedMemorySize, SMEM_BYTES);

    dim3 grid(IMW / TC, IMH / TR, NB);
    lap_merge_kernel<<<grid, NTHREADS, SMEM_BYTES>>>(x, out);
}

// round 12
// speedup vs baseline: 2.0228x; 1.1222x over previous
#include <cuda_runtime.h>
#include <cstddef>

#define IMH 1024
#define IMW 1024
#define SFRAMES 8
#define NB 4
#define TR 32            // tile rows (output)
#define TC 64            // tile cols
#define NTHREADS 256
#define GH (TR + 8)      // 40 rows incl vertical halo
#define GWF (TC + 8)     // 72: gray tile width incl horizontal halo (floats)
#define NT4 (GH * (GWF / 4))   // 720 float4 gray-load tasks (18 per row)
#define NHT (GH * (TC / 4))    // 640 hconv tasks

// smem layout (floats): sG[GH*GWF] | sHA[GH*TC] | sHB[GH*TC]
#define SMEM_FLOATS (GH * GWF + 2 * GH * TC)
#define SMEM_BYTES  (SMEM_FLOATS * 4)      // 32,000 B

__device__ __forceinline__ int reflect101(int i, int n) {
    if (i < 0) i = -i;
    if (i >= n) i = 2 * n - 2 - i;
    return i;
}

// ============================================================================
// Fused: 8-frame laplacian-of-gaussian + argmax + L1-hot winner RGB tracking
// Phase 3: 4-row x 2-col blocking, 12-row float2 sliding window (24 B/px LDS).
// ============================================================================
extern "C" __global__ void __launch_bounds__(NTHREADS, 4)
lap_merge_kernel(const float* __restrict__ x, float* __restrict__ out)
{
    extern __shared__ float smem[];
    float* sG  = smem;                      // GH x GWF gray (+halo)
    float* sHA = smem + GH * GWF;           // GH x TC horizontal A-filtered
    float* sHB = sHA + GH * TC;             // GH x TC horizontal B-filtered

    const int tid = threadIdx.x;
    const int b   = blockIdx.z;
    const int hr0 = blockIdx.y * TR;
    const int wc0 = blockIdx.x * TC;
    const size_t HW = (size_t)IMH * IMW;
    const float ONE3 = 0.33333334f;
    const bool interior = (blockIdx.x != 0) && ((int)blockIdx.x != (int)gridDim.x - 1);

    // per-thread state: 8 px = 4 rows x 2 consecutive cols
    const int r0 = (tid >> 5) * 4;          // 8 warps x 4 rows = 32 rows
    const int cg = tid & 31;                // 32 col-groups x 2 = 64 cols

    float bestLap[4][2], bR[4][2], bG[4][2], bB[4][2];
#pragma unroll
    for (int rr = 0; rr < 4; rr++)
#pragma unroll
        for (int o = 0; o < 2; o++) bestLap[rr][o] = -3.0e38f;

    for (int s = 0; s < SFRAMES; s++) {
        const float* __restrict__ xf = x + ((size_t)(b * SFRAMES + s)) * 3 * HW;

        // ==== Phase 1: gray tile load (flat, high-MLP) ====
        if (interior) {
#pragma unroll
            for (int k = 0; k < 3; k++) {
                const int t = tid + k * NTHREADS;
                if (t < NT4) {
                    const int r  = t / (GWF / 4);
                    const int c4 = t - r * (GWF / 4);
                    const int gr = reflect101(hr0 - 4 + r, IMH);
                    const float* __restrict__ p = xf + (size_t)gr * IMW + (wc0 - 4 + c4 * 4);
                    float4 a  = *reinterpret_cast<const float4*>(p);
                    float4 bq = *reinterpret_cast<const float4*>(p + HW);
                    float4 c  = *reinterpret_cast<const float4*>(p + 2 * HW);
                    float4 g;
                    g.x = (a.x + bq.x + c.x) * ONE3;
                    g.y = (a.y + bq.y + c.y) * ONE3;
                    g.z = (a.z + bq.z + c.z) * ONE3;
                    g.w = (a.w + bq.w + c.w) * ONE3;
                    *reinterpret_cast<float4*>(&sG[r * GWF + c4 * 4]) = g;
                }
            }
        } else {
            for (int i = tid; i < GH * GWF; i += NTHREADS) {
                const int r = i / GWF;
                const int c = i - r * GWF;
                const int gr = reflect101(hr0 - 4 + r, IMH);
                const int gc = reflect101(wc0 - 4 + c, IMW);
                const float* __restrict__ p = xf + (size_t)gr * IMW + gc;
                sG[i] = (__ldg(p) + __ldg(p + HW) + __ldg(p + 2 * HW)) * ONE3;
            }
        }
        __syncthreads();

        // ==== Phase 2: horizontal 9-tap A/B from sG -> sHA/sHB ====
#pragma unroll
        for (int k = 0; k < 3; k++) {
            const int t = tid + k * NTHREADS;
            if (t < NHT) {
                const int r  = t / (TC / 4);
                const int c2 = t - r * (TC / 4);
                float w[12];
#pragma unroll
                for (int j = 0; j < 12; j += 4)
                    *reinterpret_cast<float4*>(&w[j]) =
                        *reinterpret_cast<const float4*>(&sG[r * GWF + c2 * 4 + j]);
                float4 hA4, hB4;
#pragma unroll
                for (int o = 0; o < 4; o++) {
                    float p1 = w[o + 3] + w[o + 5];
                    float p2 = w[o + 2] + w[o + 6];
                    float p3 = w[o + 1] + w[o + 7];
                    float p4 = w[o + 0] + w[o + 8];
                    float ctr = w[o + 4];
                    (&hA4.x)[o] =  4.375f * ctr + 3.5f  * p1 + 1.75f * p2 + 0.5f  * p3 + 0.0625f * p4;
                    (&hB4.x)[o] = -0.625f * ctr - 0.25f * p1 + 0.25f * p2 + 0.25f * p3 + 0.0625f * p4;
                }
                *reinterpret_cast<float4*>(&sHA[r * TC + c2 * 4]) = hA4;
                *reinterpret_cast<float4*>(&sHB[r * TC + c2 * 4]) = hB4;
            }
        }
        __syncthreads();

        // ==== Phase 3: vertical 9-tap (B on hA + A on hB), 12-row window + argmax ====
        {
            const float wAv[9] = {0.0625f, 0.5f, 1.75f, 3.5f, 4.375f, 3.5f, 1.75f, 0.5f, 0.0625f};
            const float wBv[9] = {0.0625f, 0.25f, 0.25f, -0.25f, -0.625f, -0.25f, 0.25f, 0.25f, 0.0625f};
            float acc[4][2];
#pragma unroll
            for (int rr = 0; rr < 4; rr++) { acc[rr][0] = 0.f; acc[rr][1] = 0.f; }

#pragma unroll
            for (int j = 0; j < 12; j++) {
                const float2 ha = *reinterpret_cast<const float2*>(&sHA[(r0 + j) * TC + cg * 2]);
                const float2 hb = *reinterpret_cast<const float2*>(&sHB[(r0 + j) * TC + cg * 2]);
#pragma unroll
                for (int rr = 0; rr < 4; rr++) {
                    const int jj = j - rr;
                    if (jj >= 0 && jj <= 8) {     // static after unroll
                        acc[rr][0] += wBv[jj] * ha.x + wAv[jj] * hb.x;
                        acc[rr][1] += wBv[jj] * ha.y + wAv[jj] * hb.y;
                    }
                }
            }
#pragma unroll
            for (int rr = 0; rr < 4; rr++) {
                const size_t pix = (size_t)(hr0 + r0 + rr) * IMW + (wc0 + cg * 2);
#pragma unroll
                for (int o = 0; o < 2; o++) {
                    if (acc[rr][o] > bestLap[rr][o]) {  // strict > == first-max (jnp.argmax)
                        bestLap[rr][o] = acc[rr][o];
                        // winner RGB reload: bytes just read by phase 1 -> L1 hit
                        const float* __restrict__ xw = xf + pix + o;
                        bR[rr][o] = __ldg(xw);
                        bG[rr][o] = __ldg(xw + HW);
                        bB[rr][o] = __ldg(xw + 2 * HW);
                    }
                }
            }
        }
        __syncthreads();   // sG/sHA/sHB reused by next frame
    }

    // ==== Epilogue: write winner RGB (b, c, h, w) as float2 per row/channel ====
#pragma unroll
    for (int rr = 0; rr < 4; rr++) {
        const size_t obase = ((size_t)(b * 3) * IMH + (hr0 + r0 + rr)) * IMW + wc0 + cg * 2;
        *reinterpret_cast<float2*>(out + obase)          = make_float2(bR[rr][0], bR[rr][1]);
        *reinterpret_cast<float2*>(out + obase + HW)     = make_float2(bG[rr][0], bG[rr][1]);
        *reinterpret_cast<float2*>(out + obase + 2 * HW) = make_float2(bB[rr][0], bB[rr][1]);
    }
}

// ============================================================================
extern "C" void kernel_launch(void* const* d_in, const int* in_sizes, int n_in,
                              void* d_out, int out_size)
{
    const float* x = (const float*)d_in[0];
    float* out = (float*)d_out;

    cudaFuncSetAttribute(lap_merge_kernel,
                         cudaFuncAttributeMaxDynamicSharedMemorySize, SMEM_BYTES);

    dim3 grid(IMW / TC, IMH / TR, NB);
    lap_merge_kernel<<<grid, NTHREADS, SMEM_BYTES>>>(x, out);
}